// round 6
// baseline (speedup 1.0000x reference)
#include <cuda_runtime.h>

// RiRoIAlign for GB300 — channel-paired gather with merged x-tap float2 loads.
// features: (B=2, Ctot=256, H=256, W=256) fp32
// rois: (512, 6) fp32 = [batch, cx, cy, w, h, theta]
// out: (512, 256, 7, 7) fp32, channel = c*8 + o  (C=32, O=8)
//
// Per bilinear sample, the two x-taps (x_low, x_low+1) are fetched with one
// 8B-aligned float2 load (weights baked per alignment parity); odd-parity
// samples add one predicated scalar tail. 3 loads/sample/channel avg vs 4.

#define HH 256
#define WW 256
#define CT 256
#define OO 8
#define NBIN 49
#define NS 196
#define HW (HH * WW)
#define NITEM (OO * NBIN)        // 392
#define NCH 4                    // channels per CTA
#define NOUT (NCH * NITEM)       // 1568

__global__ __launch_bounds__(256, 5)
void riroi_kernel(const float* __restrict__ features,
                  const float* __restrict__ rois,
                  float* __restrict__ out)
{
    __shared__ int4   sidx[NS];   // rowL(=yl*W), rowH(=yh*W), xb(=xl&~1), xt(tail col)
    __shared__ float4 swx[NS];    // {a, b, c, 0}: float2 weights + tail weight
    __shared__ float2 swy[NS];    // {hy*vm, ly*vm}
    __shared__ float  acc[NOUT];

    const int r   = blockIdx.x;
    const int cg  = blockIdx.y;          // 8 groups of 4 channels
    const int tid = threadIdx.x;

    const float b_f = rois[r * 6 + 0];
    const float cwv = rois[r * 6 + 1] * 0.125f;
    const float chv = rois[r * 6 + 2] * 0.125f;
    const float rw  = fmaxf(rois[r * 6 + 3] * 0.125f, 1.0f);
    const float rh  = fmaxf(rois[r * 6 + 4] * 0.125f, 1.0f);
    const float th  = rois[r * 6 + 5];
    const int   b   = (int)b_f;

    const float st  = sinf(th);
    const float ctt = cosf(th);

    const float indf   = (th * 8.0f) / 6.283185307179586f;
    const float indflo = floorf(indf);
    const float lv     = indf - indflo;
    const float rv     = 1.0f - lv;
    int ind = (int)indflo;
    ind = ((ind % 8) + 8) % 8;

    const float bin_h = rh / 7.0f;
    const float bin_w = rw / 7.0f;

    // ---- per-sample geometry, order (py, gy, px, gx) ----
    if (tid < NS) {
        const int s  = tid;
        const int gx = s & 1;
        const int px = (s >> 1) % 7;
        const int gy = (s / 14) & 1;
        const int py = s / 28;

        const float yy = -rh * 0.5f + ((float)py + ((float)gy + 0.5f) * 0.5f) * bin_h;
        const float xx = -rw * 0.5f + ((float)px + ((float)gx + 0.5f) * 0.5f) * bin_w;

        const float x = xx * ctt - yy * st + cwv;
        const float y = xx * st + yy * ctt + chv;

        const bool valid = (y > -1.0f) && (y < 256.0f) && (x > -1.0f) && (x < 256.0f);

        const float yc = fmaxf(y, 0.0f);
        const float xc = fmaxf(x, 0.0f);
        int yl = (int)yc;
        int xl = (int)xc;
        int yh, xh;
        float yv, xv;
        if (yl >= HH - 1) { yl = HH - 1; yh = HH - 1; yv = (float)(HH - 1); }
        else              { yh = yl + 1;              yv = yc; }
        if (xl >= WW - 1) { xl = WW - 1; xh = WW - 1; xv = (float)(WW - 1); }
        else              { xh = xl + 1;              xv = xc; }

        const float ly = yv - (float)yl;
        const float lx = xv - (float)xl;
        const float hy = 1.0f - ly;
        const float hx = 1.0f - lx;
        const float vm = valid ? 1.0f : 0.0f;

        const int  xb  = xl & ~1;
        const bool odd = (xl & 1) != 0;

        // even: float2@xl covers (xl, xl+1) with (hx, lx); no tail.
        // odd:  float2@xl-1 covers (xl-1, xl) with (0, hx); tail at xh with lx.
        //       (xl == W-1 odd clamp: lx == 0 -> tail predicated off; xt=xh safe.)
        float a, bb, c;
        int xt;
        if (!odd) { a = hx;  bb = lx; c = 0.0f; xt = xb; }
        else      { a = 0.0f; bb = hx; c = lx;  xt = xh; }

        sidx[s] = make_int4(yl * WW, yh * WW, xb, xt);
        swx[s]  = make_float4(a, bb, c, 0.0f);
        swy[s]  = make_float2(hy * vm, ly * vm);
    }
    __syncthreads();

    const float* fb = features + ((size_t)b * CT + (size_t)cg * NCH * OO) * (size_t)HW;

    #pragma unroll 1
    for (int cp = 0; cp < NCH / 2; ++cp) {           // channel pairs
        const float* c0 = fb + (size_t)(cp * 2) * OO * HW;

        for (int it = tid; it < NITEM; it += 256) {
            const int plane = it / NBIN;
            const int bin   = it - plane * NBIN;
            const int py    = bin / 7;
            const int px    = bin - py * 7;
            const float* p0 = c0 + plane * HW;
            const float* p1 = p0 + OO * HW;

            float a0 = 0.0f, a1 = 0.0f;
            #pragma unroll
            for (int gy = 0; gy < 2; ++gy) {
                #pragma unroll
                for (int gx = 0; gx < 2; ++gx) {
                    const int s = ((py * 2 + gy) * 7 + px) * 2 + gx;
                    const int4   ix = sidx[s];
                    const float4 wx = swx[s];
                    const float2 wy = swy[s];

                    const float2 f0L = __ldg((const float2*)(p0 + ix.x + ix.z));
                    const float2 f0H = __ldg((const float2*)(p0 + ix.y + ix.z));
                    const float2 f1L = __ldg((const float2*)(p1 + ix.x + ix.z));
                    const float2 f1H = __ldg((const float2*)(p1 + ix.y + ix.z));

                    float d0L = wx.x * f0L.x + wx.y * f0L.y;
                    float d0H = wx.x * f0H.x + wx.y * f0H.y;
                    float d1L = wx.x * f1L.x + wx.y * f1L.y;
                    float d1H = wx.x * f1H.x + wx.y * f1H.y;

                    if (wx.z != 0.0f) {
                        d0L += wx.z * __ldg(p0 + ix.x + ix.w);
                        d0H += wx.z * __ldg(p0 + ix.y + ix.w);
                        d1L += wx.z * __ldg(p1 + ix.x + ix.w);
                        d1H += wx.z * __ldg(p1 + ix.y + ix.w);
                    }
                    a0 += wy.x * d0L + wy.y * d0H;
                    a1 += wy.x * d1L + wy.y * d1H;
                }
            }
            acc[(cp * 2 + 0) * NITEM + it] = a0;
            acc[(cp * 2 + 1) * NITEM + it] = a1;
        }
    }
    __syncthreads();

    // out[r, cg*32 .. +32, 7, 7] contiguous; j = cc*392 + o*49 + bin.
    float* ob = out + ((size_t)r * CT + (size_t)cg * NCH * OO) * (size_t)NBIN;
    for (int j = tid; j < NOUT; j += 256) {
        const int cc   = j / NITEM;
        const int rest = j - cc * NITEM;
        const int o    = rest / NBIN;
        const int bin  = rest - o * NBIN;
        const int p0   = (o - ind + 8) & 7;
        const int p1   = (p0 + 1) & 7;
        ob[j] = 0.25f * (rv * acc[cc * NITEM + p0 * NBIN + bin]
                       + lv * acc[cc * NITEM + p1 * NBIN + bin]);
    }
}

extern "C" void kernel_launch(void* const* d_in, const int* in_sizes, int n_in,
                              void* d_out, int out_size)
{
    const float* features = (const float*)d_in[0];
    const float* rois     = (const float*)d_in[1];
    float*       out      = (float*)d_out;

    const int R = in_sizes[1] / 6;
    dim3 grid((unsigned)R, 8);
    riroi_kernel<<<grid, 256>>>(features, rois, out);
}

// round 8
// speedup vs baseline: 1.0697x; 1.0697x over previous
#include <cuda_runtime.h>

// RiRoIAlign for GB300 — scalar scattered gather, one channel pair per CTA.
// features: (B=2, Ctot=256, H=256, W=256) fp32
// rois: (512, 6) fp32 = [batch, cx, cy, w, h, theta]
// out: (512, 256, 7, 7) fp32, channel = c*8 + o  (C=32, O=8)
//
// grid = (512 rois, 16 channel pairs). Each thread owns (plane, bin) items and
// accumulates both channels of the pair (scalar LDG.32 taps — wide/fused loads
// empirically lose on this access pattern). High occupancy via low reg budget.

#define HH 256
#define WW 256
#define CT 256
#define OO 8
#define NBIN 49
#define NS 196
#define HW (HH * WW)
#define NITEM (OO * NBIN)        // 392
#define NOUT (2 * NITEM)         // 784 floats, contiguous in out

__global__ __launch_bounds__(256, 6)
void riroi_kernel(const float* __restrict__ features,
                  const float* __restrict__ rois,
                  float* __restrict__ out)
{
    __shared__ int4   soff[NS];
    __shared__ float4 swt[NS];
    __shared__ float  acc[NOUT];

    const int r   = blockIdx.x;
    const int cg  = blockIdx.y;          // 16 channel pairs
    const int tid = threadIdx.x;

    const float b_f = rois[r * 6 + 0];
    const float cwv = rois[r * 6 + 1] * 0.125f;
    const float chv = rois[r * 6 + 2] * 0.125f;
    const float rw  = fmaxf(rois[r * 6 + 3] * 0.125f, 1.0f);
    const float rh  = fmaxf(rois[r * 6 + 4] * 0.125f, 1.0f);
    const float th  = rois[r * 6 + 5];
    const int   b   = (int)b_f;

    const float st  = sinf(th);
    const float ctt = cosf(th);

    const float indf   = (th * 8.0f) / 6.283185307179586f;
    const float indflo = floorf(indf);
    const float lv     = indf - indflo;
    const float rv     = 1.0f - lv;
    int ind = (int)indflo;
    ind = ((ind % 8) + 8) % 8;

    const float bin_h = rh / 7.0f;
    const float bin_w = rw / 7.0f;

    // ---- per-sample geometry, order (py, gy, px, gx) ----
    if (tid < NS) {
        const int s  = tid;
        const int gx = s & 1;
        const int px = (s >> 1) % 7;
        const int gy = (s / 14) & 1;
        const int py = s / 28;

        const float yy = -rh * 0.5f + ((float)py + ((float)gy + 0.5f) * 0.5f) * bin_h;
        const float xx = -rw * 0.5f + ((float)px + ((float)gx + 0.5f) * 0.5f) * bin_w;

        const float x = xx * ctt - yy * st + cwv;
        const float y = xx * st + yy * ctt + chv;

        const bool valid = (y > -1.0f) && (y < 256.0f) && (x > -1.0f) && (x < 256.0f);

        const float yc = fmaxf(y, 0.0f);
        const float xc = fmaxf(x, 0.0f);
        int yl = (int)yc;
        int xl = (int)xc;
        int yh, xh;
        float yv, xv;
        if (yl >= HH - 1) { yl = HH - 1; yh = HH - 1; yv = (float)(HH - 1); }
        else              { yh = yl + 1;              yv = yc; }
        if (xl >= WW - 1) { xl = WW - 1; xh = WW - 1; xv = (float)(WW - 1); }
        else              { xh = xl + 1;              xv = xc; }

        const float ly = yv - (float)yl;
        const float lx = xv - (float)xl;
        const float hy = 1.0f - ly;
        const float hx = 1.0f - lx;
        const float vm = valid ? 1.0f : 0.0f;

        swt[s]  = make_float4(hy * hx * vm, hy * lx * vm, ly * hx * vm, ly * lx * vm);
        soff[s] = make_int4(yl * WW + xl, yl * WW + xh, yh * WW + xl, yh * WW + xh);
    }
    __syncthreads();

    // base: features[b, cg*2*8 + {0,1}*8 + plane, :, :]
    const float* p0b = features + ((size_t)b * CT + (size_t)cg * 16) * (size_t)HW;

    for (int it = tid; it < NITEM; it += 256) {
        const int plane = it / NBIN;
        const int bin   = it - plane * NBIN;
        const int py    = bin / 7;
        const int px    = bin - py * 7;
        const float* p0 = p0b + plane * HW;
        const float* p1 = p0 + OO * HW;      // second channel of the pair

        float a0 = 0.0f, a1 = 0.0f;
        #pragma unroll
        for (int gy = 0; gy < 2; ++gy) {
            #pragma unroll
            for (int gx = 0; gx < 2; ++gx) {
                const int s = ((py * 2 + gy) * 7 + px) * 2 + gx;
                const int4   o = soff[s];
                const float4 w = swt[s];
                const float t00 = __ldg(p0 + o.x);
                const float t01 = __ldg(p0 + o.y);
                const float t02 = __ldg(p0 + o.z);
                const float t03 = __ldg(p0 + o.w);
                const float t10 = __ldg(p1 + o.x);
                const float t11 = __ldg(p1 + o.y);
                const float t12 = __ldg(p1 + o.z);
                const float t13 = __ldg(p1 + o.w);
                a0 += w.x * t00 + w.y * t01 + w.z * t02 + w.w * t03;
                a1 += w.x * t10 + w.y * t11 + w.z * t12 + w.w * t13;
            }
        }
        acc[it]         = a0;
        acc[NITEM + it] = a1;
    }
    __syncthreads();

    // out[r, cg*16 .. +16, 7, 7] is one contiguous 784-float run;
    // j = cc*392 + o*49 + bin == (cc*8+o)*49 + bin matches memory order.
    // NOUT = 784 = 3*256 + 16 -> need 4 strided passes (R7 bug: had 3).
    float* ob = out + ((size_t)r * CT + (size_t)cg * 16) * (size_t)NBIN;
    #pragma unroll
    for (int jj = 0; jj < 4; ++jj) {
        const int j = jj * 256 + tid;
        if (j < NOUT) {
            const int cc   = j / NITEM;
            const int rest = j - cc * NITEM;
            const int o    = rest / NBIN;
            const int bin  = rest - o * NBIN;
            const int p0i  = (o - ind + 8) & 7;
            const int p1i  = (p0i + 1) & 7;
            ob[j] = 0.25f * (rv * acc[cc * NITEM + p0i * NBIN + bin]
                           + lv * acc[cc * NITEM + p1i * NBIN + bin]);
        }
    }
}

extern "C" void kernel_launch(void* const* d_in, const int* in_sizes, int n_in,
                              void* d_out, int out_size)
{
    const float* features = (const float*)d_in[0];
    const float* rois     = (const float*)d_in[1];
    float*       out      = (float*)d_out;

    const int R = in_sizes[1] / 6;
    dim3 grid((unsigned)R, 16);
    riroi_kernel<<<grid, 256>>>(features, rois, out);
}

// round 9
// speedup vs baseline: 1.3542x; 1.2660x over previous
#include <cuda_runtime.h>

// RiRoIAlign for GB300 — tap-parallel warp layout for intra-LDG line dedup.
// features: (B=2, Ctot=256, H=256, W=256) fp32
// rois: (512, 6) fp32 = [batch, cx, cy, w, h, theta]
// out: (512, 256, 7, 7) fp32, channel = c*8 + o  (C=32, O=8)
//
// grid = (512 rois, 16 channel pairs). Warp = 4 consecutive (plane,bin) items;
// lane = (item(2b), sample-in-bin(2b), x-side(1b)). Each lane loads the row-low
// and row-high taps at its x-side (scalar LDG.32), weights folded so
// v = wx * (hy'*t_low + ly'*t_high); bin value = shfl-sum over 8 lanes.
// One LDG instruction covers 32 spatially-clustered taps -> high line dedup.

#define HH 256
#define WW 256
#define CT 256
#define OO 8
#define NBIN 49
#define NS 196
#define HW (HH * WW)
#define NITEM (OO * NBIN)        // 392
#define NOUT (2 * NITEM)         // 784

__global__ __launch_bounds__(256, 6)
void riroi_kernel(const float* __restrict__ features,
                  const float* __restrict__ rois,
                  float* __restrict__ out)
{
    __shared__ int4   soff[NS];   // (yl*W+xl, yl*W+xh, yh*W+xl, yh*W+xh), bin-major
    __shared__ float4 swt[NS];    // {hx, lx, hy*vm, ly*vm}
    __shared__ float  acc[NOUT];

    const int r   = blockIdx.x;
    const int cg  = blockIdx.y;          // 16 channel pairs
    const int tid = threadIdx.x;

    const float b_f = rois[r * 6 + 0];
    const float cwv = rois[r * 6 + 1] * 0.125f;
    const float chv = rois[r * 6 + 2] * 0.125f;
    const float rw  = fmaxf(rois[r * 6 + 3] * 0.125f, 1.0f);
    const float rh  = fmaxf(rois[r * 6 + 4] * 0.125f, 1.0f);
    const float th  = rois[r * 6 + 5];
    const int   b   = (int)b_f;

    const float st  = sinf(th);
    const float ctt = cosf(th);

    const float indf   = (th * 8.0f) / 6.283185307179586f;
    const float indflo = floorf(indf);
    const float lv     = indf - indflo;
    const float rv     = 1.0f - lv;
    int ind = (int)indflo;
    ind = ((ind % 8) + 8) % 8;

    const float bin_h = rh / 7.0f;
    const float bin_w = rw / 7.0f;

    // ---- geometry, bin-major: s = bin*4 + (gy*2+gx) ----
    if (tid < NS) {
        const int s   = tid;
        const int gx  = s & 1;
        const int gy  = (s >> 1) & 1;
        const int bin = s >> 2;
        const int py  = bin / 7;
        const int px  = bin - py * 7;

        const float yy = -rh * 0.5f + ((float)py + ((float)gy + 0.5f) * 0.5f) * bin_h;
        const float xx = -rw * 0.5f + ((float)px + ((float)gx + 0.5f) * 0.5f) * bin_w;

        const float x = xx * ctt - yy * st + cwv;
        const float y = xx * st + yy * ctt + chv;

        const bool valid = (y > -1.0f) && (y < 256.0f) && (x > -1.0f) && (x < 256.0f);

        const float yc = fmaxf(y, 0.0f);
        const float xc = fmaxf(x, 0.0f);
        int yl = (int)yc;
        int xl = (int)xc;
        int yh, xh;
        float yv, xv;
        if (yl >= HH - 1) { yl = HH - 1; yh = HH - 1; yv = (float)(HH - 1); }
        else              { yh = yl + 1;              yv = yc; }
        if (xl >= WW - 1) { xl = WW - 1; xh = WW - 1; xv = (float)(WW - 1); }
        else              { xh = xl + 1;              xv = xc; }

        const float ly = yv - (float)yl;
        const float lx = xv - (float)xl;
        const float hy = 1.0f - ly;
        const float hx = 1.0f - lx;
        const float vm = valid ? 1.0f : 0.0f;

        swt[s]  = make_float4(hx, lx, hy * vm, ly * vm);
        soff[s] = make_int4(yl * WW + xl, yl * WW + xh, yh * WW + xl, yh * WW + xh);
    }
    __syncthreads();

    // base: features[b, cg*16 + {0,1}*8 + plane, :, :]
    const float* fbase = features + ((size_t)b * CT + (size_t)cg * 16) * (size_t)HW;

    const int warp = tid >> 5;
    const int lane = tid & 31;
    const int isub = lane >> 3;          // item within warp's group of 4
    const int q    = (lane >> 1) & 3;    // sample within bin
    const int side = lane & 1;           // x-side: 0 -> xl, 1 -> xh

    // 98 warp-passes of 4 items; warp w takes gBase = w*4 + p*32
    for (int gBase = warp * 4; gBase < NITEM; gBase += 32) {
        const int g     = gBase + isub;
        const int plane = g / NBIN;
        const int bin   = g - plane * NBIN;
        const int s     = bin * 4 + q;

        const int4   o = soff[s];
        const float4 w = swt[s];
        const int   offL = side ? o.y : o.x;
        const int   offH = side ? o.w : o.z;
        const float wx   = side ? w.y : w.x;

        const float* p0 = fbase + plane * HW;
        const float* p1 = p0 + OO * HW;

        const float t0L = __ldg(p0 + offL);
        const float t0H = __ldg(p0 + offH);
        const float t1L = __ldg(p1 + offL);
        const float t1H = __ldg(p1 + offH);

        float v0 = wx * (w.z * t0L + w.w * t0H);
        float v1 = wx * (w.z * t1L + w.w * t1H);

        // sum the 8 lanes (4 samples x 2 sides) of this bin
        v0 += __shfl_xor_sync(0xFFFFFFFFu, v0, 1);
        v1 += __shfl_xor_sync(0xFFFFFFFFu, v1, 1);
        v0 += __shfl_xor_sync(0xFFFFFFFFu, v0, 2);
        v1 += __shfl_xor_sync(0xFFFFFFFFu, v1, 2);
        v0 += __shfl_xor_sync(0xFFFFFFFFu, v0, 4);
        v1 += __shfl_xor_sync(0xFFFFFFFFu, v1, 4);

        if ((lane & 7) == 0) {
            acc[g]         = v0;
            acc[NITEM + g] = v1;
        }
    }
    __syncthreads();

    // out[r, cg*16 .. +16, 7, 7]: contiguous 784 floats; j = cc*392 + o*49 + bin.
    float* ob = out + ((size_t)r * CT + (size_t)cg * 16) * (size_t)NBIN;
    #pragma unroll
    for (int jj = 0; jj < 4; ++jj) {
        const int j = jj * 256 + tid;
        if (j < NOUT) {
            const int cc   = j / NITEM;
            const int rest = j - cc * NITEM;
            const int o    = rest / NBIN;
            const int bin  = rest - o * NBIN;
            const int p0i  = (o - ind + 8) & 7;
            const int p1i  = (p0i + 1) & 7;
            ob[j] = 0.25f * (rv * acc[cc * NITEM + p0i * NBIN + bin]
                           + lv * acc[cc * NITEM + p1i * NBIN + bin]);
        }
    }
}

extern "C" void kernel_launch(void* const* d_in, const int* in_sizes, int n_in,
                              void* d_out, int out_size)
{
    const float* features = (const float*)d_in[0];
    const float* rois     = (const float*)d_in[1];
    float*       out      = (float*)d_out;

    const int R = in_sizes[1] / 6;
    dim3 grid((unsigned)R, 16);
    riroi_kernel<<<grid, 256>>>(features, rois, out);
}